// round 7
// baseline (speedup 1.0000x reference)
#include <cuda_runtime.h>
#include <cuda_bf16.h>
#include <math.h>

// Problem constants
#define MAXN 50000
#define MAXE 800000
#define F1   128   // F_IN and H
#define F2   64    // C

// ---------------- scratch (__device__ globals; no allocs allowed) --------------
__device__ __align__(16) float g_agg[MAXN * F1];   // mean-aggregated features
__device__ __align__(16) float g_h1 [MAXN * F1];   // SAGE1 output
__device__ __align__(16) float g_h2 [MAXN * F2];   // SAGE2 output (pre-softmax)
__device__ __align__(16) float g_y  [MAXN * F2];   // softmax(h2)@Wg * dinv[src]
__device__ __align__(16) float g_dinv[MAXN];       // rsqrt(indeg+1)
__device__ __align__(16) int2  g_edge[MAXE];       // packed (src,dst)
__device__ __align__(16) int   g_csrc[MAXE];       // CSR: src ids grouped by dst
__device__ __align__(16) int   g_cnt [MAXN];       // in-degree (int)
__device__ __align__(16) int   g_rowptr[MAXN + 1];
__device__ __align__(16) int   g_cursor[MAXN];
__device__ int g_isi64;                            // 1 if edge_index really int64

// ---------------- init ---------------------------------------------------------
__global__ void init_kernel(int n) {
    int i = blockIdx.x * blockDim.x + threadIdx.x;
    if (i < n) g_cnt[i] = 0;
}

// ---------------- probe: is edge_index int64 or int32? -------------------------
// int64 node ids are < 2^31. int32 data misread as int64 gives lo + hi*2^32
// with hi a node id (rarely 0), so at least one of 64 probes is >= 2^31.
__global__ void probe_kernel(const void* __restrict__ idxv) {
    if (threadIdx.x == 0 && blockIdx.x == 0) {
        const long long* p = (const long long*)idxv;
        int ok = 1;
        for (int i = 0; i < 64; i++) {
            long long v = p[i];
            if (v < 0 || v >= 2147483648LL) { ok = 0; break; }
        }
        g_isi64 = ok;
    }
}

// ---------------- decode: edge_index -> int2, degree count (int atomics) -------
__global__ void decode_kernel(const void* __restrict__ idxv, int E) {
    int e = blockIdx.x * blockDim.x + threadIdx.x;
    if (e >= E) return;
    int s, d;
    if (g_isi64) {
        const long long* p = (const long long*)idxv;
        s = (int)p[e];
        d = (int)p[E + e];
    } else {
        const int* p = (const int*)idxv;
        s = p[e];
        d = p[E + e];
    }
    g_edge[e] = make_int2(s, d);
    atomicAdd(&g_cnt[d], 1);
}

// ---------------- single-block exclusive scan (warp-scan based) ----------------
__global__ void __launch_bounds__(1024) scan_kernel(int n, int E) {
    __shared__ int wsum[32];
    __shared__ int s_carry;
    int tid = threadIdx.x, lane = tid & 31, wid = tid >> 5;
    if (tid == 0) s_carry = 0;
    __syncthreads();
    for (int base = 0; base < n; base += 1024) {
        int i = base + tid;
        int v = (i < n) ? g_cnt[i] : 0;
        int x = v;
#pragma unroll
        for (int o = 1; o < 32; o <<= 1) {
            int t = __shfl_up_sync(0xffffffffu, x, o);
            if (lane >= o) x += t;
        }
        if (lane == 31) wsum[wid] = x;
        __syncthreads();
        if (wid == 0) {
            int y = wsum[lane];
#pragma unroll
            for (int o = 1; o < 32; o <<= 1) {
                int t = __shfl_up_sync(0xffffffffu, y, o);
                if (lane >= o) y += t;
            }
            wsum[lane] = y;
        }
        __syncthreads();
        int excl = s_carry + (wid ? wsum[wid - 1] : 0) + x - v;
        if (i < n) { g_rowptr[i] = excl; g_cursor[i] = excl; }
        __syncthreads();
        if (tid == 0) s_carry += wsum[31];
        __syncthreads();
    }
    if (tid == 0) g_rowptr[n] = E;
}

// ---------------- CSR fill ------------------------------------------------------
__global__ void fill_kernel(int E) {
    int e = blockIdx.x * blockDim.x + threadIdx.x;
    if (e >= E) return;
    int2 ed = g_edge[e];
    int pos = atomicAdd(&g_cursor[ed.y], 1);
    g_csrc[pos] = ed.x;
}

// ---------------- SAGE mean-aggregation gather (warp per node, F=128) ----------
template <bool FIRST>
__global__ void __launch_bounds__(256)
gather_kernel(const float* __restrict__ xparam, int n) {
    int w = (blockIdx.x * blockDim.x + threadIdx.x) >> 5;
    if (w >= n) return;
    int lane = threadIdx.x & 31;
    const float* __restrict__ feat = FIRST ? xparam : g_h1;

    int beg = g_rowptr[w], end = g_rowptr[w + 1];
    float4 acc = make_float4(0.f, 0.f, 0.f, 0.f);
    for (int chunk = beg; chunk < end; chunk += 32) {
        int myidx = (chunk + lane < end) ? g_csrc[chunk + lane] : 0;
        int m = min(32, end - chunk);
        for (int j = 0; j < m; j++) {
            int s = __shfl_sync(0xffffffffu, myidx, j);
            float4 v = *reinterpret_cast<const float4*>(feat + (size_t)s * F1 + lane * 4);
            acc.x += v.x; acc.y += v.y; acc.z += v.z; acc.w += v.w;
        }
    }
    float r = 1.f / fmaxf((float)(end - beg), 1.f);
    acc.x *= r; acc.y *= r; acc.z *= r; acc.w *= r;
    *reinterpret_cast<float4*>(g_agg + (size_t)w * F1 + lane * 4) = acc;
}

// ---------------- SAGE dual-GEMM: out = act(mean@Wl + bl + x@Wr) ---------------
template <int LAYER>
__global__ void __launch_bounds__(256)
sage_gemm_kernel(const float* __restrict__ xparam,
                 const float* __restrict__ Wl,
                 const float* __restrict__ bl,
                 const float* __restrict__ Wr, int n) {
    constexpr int FIN  = 128;
    constexpr int FOUT = (LAYER == 1) ? 128 : 64;
    constexpr bool RELU = (LAYER == 1);
    constexpr int TM = 32, KT = 32;
    constexpr int HV = FOUT / 32;         // 4 (layer1) or 2 (layer2)

    __shared__ __align__(16) float sWl[KT][FOUT];
    __shared__ __align__(16) float sWr[KT][FOUT];
    __shared__ __align__(16) float sM[TM][KT];
    __shared__ __align__(16) float sX[TM][KT];

    const float* __restrict__ xin = (LAYER == 1) ? xparam : g_h1;
    float* __restrict__ out = (LAYER == 1) ? g_h1 : g_h2;

    int tid = threadIdx.x;
    int tx = tid & 31;
    int ty = tid >> 5;
    int nbase = blockIdx.x * TM;

    float acc[4][HV];
#pragma unroll
    for (int m = 0; m < 4; m++)
#pragma unroll
        for (int j = 0; j < HV; j++) acc[m][j] = 0.f;

    for (int kt = 0; kt < FIN; kt += KT) {
#pragma unroll
        for (int i = tid; i < KT * FOUT / 4; i += 256) {
            int k = i / (FOUT / 4);
            int h = (i % (FOUT / 4)) * 4;
            *reinterpret_cast<float4*>(&sWl[k][h]) =
                *reinterpret_cast<const float4*>(&Wl[(size_t)(kt + k) * FOUT + h]);
            *reinterpret_cast<float4*>(&sWr[k][h]) =
                *reinterpret_cast<const float4*>(&Wr[(size_t)(kt + k) * FOUT + h]);
        }
        {
            int i = tid;                  // TM*KT/4 == 256 exactly
            int nl = i / (KT / 4);
            int k  = (i % (KT / 4)) * 4;
            int node = nbase + nl;
            float4 a = make_float4(0.f, 0.f, 0.f, 0.f);
            float4 xx = a;
            if (node < n) {
                a  = *reinterpret_cast<const float4*>(&g_agg[(size_t)node * FIN + kt + k]);
                xx = *reinterpret_cast<const float4*>(&xin  [(size_t)node * FIN + kt + k]);
            }
            *reinterpret_cast<float4*>(&sM[nl][k]) = a;
            *reinterpret_cast<float4*>(&sX[nl][k]) = xx;
        }
        __syncthreads();

#pragma unroll
        for (int k = 0; k < KT; k++) {
            float wl[HV], wr[HV];
            if constexpr (HV == 4) {
                float4 t1 = *reinterpret_cast<const float4*>(&sWl[k][tx * 4]);
                wl[0] = t1.x; wl[1] = t1.y; wl[2] = t1.z; wl[3] = t1.w;
                float4 t2 = *reinterpret_cast<const float4*>(&sWr[k][tx * 4]);
                wr[0] = t2.x; wr[1] = t2.y; wr[2] = t2.z; wr[3] = t2.w;
            } else {
                float2 t1 = *reinterpret_cast<const float2*>(&sWl[k][tx * 2]);
                wl[0] = t1.x; wl[1] = t1.y;
                float2 t2 = *reinterpret_cast<const float2*>(&sWr[k][tx * 2]);
                wr[0] = t2.x; wr[1] = t2.y;
            }
            float rm[4], rx[4];
#pragma unroll
            for (int m = 0; m < 4; m++) {
                rm[m] = sM[ty * 4 + m][k];
                rx[m] = sX[ty * 4 + m][k];
            }
#pragma unroll
            for (int m = 0; m < 4; m++)
#pragma unroll
                for (int j = 0; j < HV; j++)
                    acc[m][j] += rm[m] * wl[j] + rx[m] * wr[j];
        }
        __syncthreads();
    }

#pragma unroll
    for (int m = 0; m < 4; m++) {
        int node = nbase + ty * 4 + m;
        if (node < n) {
#pragma unroll
            for (int j = 0; j < HV; j++) {
                float o = acc[m][j] + bl[tx * HV + j];
                if (RELU) o = fmaxf(o, 0.f);
                out[(size_t)node * FOUT + tx * HV + j] = o;
            }
        }
    }
}

// ---------------- fused softmax + Wg GEMM + self-loop term + bias --------------
__global__ void __launch_bounds__(256)
softmax_gcn_kernel(const float* __restrict__ Wg, const float* __restrict__ bg,
                   float* __restrict__ out, int n) {
    __shared__ __align__(16) float sW[F2 * F2];
    __shared__ float sB[F2];
    __shared__ float sS[8][F2];
    int tid = threadIdx.x;
#pragma unroll
    for (int i = tid; i < F2 * F2 / 4; i += 256)
        reinterpret_cast<float4*>(sW)[i] = reinterpret_cast<const float4*>(Wg)[i];
    if (tid < F2) sB[tid] = bg[tid];
    __syncthreads();

    int warp = tid >> 5, lane = tid & 31;
    int node = blockIdx.x * 8 + warp;
    if (node >= n) return;

    float v0 = g_h2[(size_t)node * F2 + lane];
    float v1 = g_h2[(size_t)node * F2 + 32 + lane];
    float mx = fmaxf(v0, v1);
#pragma unroll
    for (int o = 16; o; o >>= 1) mx = fmaxf(mx, __shfl_xor_sync(0xffffffffu, mx, o));
    float e0 = __expf(v0 - mx), e1 = __expf(v1 - mx);
    float sm = e0 + e1;
#pragma unroll
    for (int o = 16; o; o >>= 1) sm += __shfl_xor_sync(0xffffffffu, sm, o);
    float inv = 1.f / sm;
    sS[warp][lane]      = e0 * inv;
    sS[warp][lane + 32] = e1 * inv;
    __syncwarp();

    float a0 = 0.f, a1 = 0.f;
#pragma unroll
    for (int k = 0; k < F2; k++) {
        float s = sS[warp][k];
        a0 += s * sW[k * F2 + lane];
        a1 += s * sW[k * F2 + lane + 32];
    }
    float di = rsqrtf((float)g_cnt[node] + 1.0f);   // deg = indeg + self loop
    float y0 = a0 * di, y1 = a1 * di;
    g_y[(size_t)node * F2 + lane]      = y0;
    g_y[(size_t)node * F2 + lane + 32] = y1;
    if (lane == 0) g_dinv[node] = di;
    out[(size_t)node * F2 + lane]      = y0 * di + sB[lane];
    out[(size_t)node * F2 + lane + 32] = y1 * di + sB[lane + 32];
}

// ---------------- GCN gather: out[i] += dinv[i] * sum_{s in N(i)} y[s] ---------
__global__ void __launch_bounds__(256)
gcn_gather_kernel(float* __restrict__ out, int n) {
    int w = (blockIdx.x * blockDim.x + threadIdx.x) >> 5;
    if (w >= n) return;
    int lane = threadIdx.x & 31;

    int beg = g_rowptr[w], end = g_rowptr[w + 1];
    float2 acc = make_float2(0.f, 0.f);
    for (int chunk = beg; chunk < end; chunk += 32) {
        int myidx = (chunk + lane < end) ? g_csrc[chunk + lane] : 0;
        int m = min(32, end - chunk);
        for (int j = 0; j < m; j++) {
            int s = __shfl_sync(0xffffffffu, myidx, j);
            float2 v = *reinterpret_cast<const float2*>(g_y + (size_t)s * F2 + lane * 2);
            acc.x += v.x; acc.y += v.y;
        }
    }
    float di = g_dinv[w];
    float* o = out + (size_t)w * F2 + lane * 2;
    o[0] += di * acc.x;
    o[1] += di * acc.y;
}

// ---------------- launch -------------------------------------------------------
extern "C" void kernel_launch(void* const* d_in, const int* in_sizes, int n_in,
                              void* d_out, int out_size) {
    // Resolve inputs BY SIZE (robust to metadata ordering).
    const float* x   = nullptr;
    const void*  idx = nullptr;
    const float *W1l = nullptr, *W1r = nullptr, *b1l = nullptr;
    const float *W2l = nullptr, *W2r = nullptr, *b2l = nullptr;
    const float *Wg  = nullptr, *bg  = nullptr;

    for (int i = 0; i < n_in; i++) {
        int sz = in_sizes[i];
        const void* p = d_in[i];
        switch (sz) {
            case 6400000: x = (const float*)p; break;
            case 1600000: idx = p; break;
            case 16384:  if (!W1l) W1l = (const float*)p; else W1r = (const float*)p; break;
            case 8192:   if (!W2l) W2l = (const float*)p; else W2r = (const float*)p; break;
            case 4096:   Wg = (const float*)p; break;
            case 128:    b1l = (const float*)p; break;
            case 64:     if (!b2l) b2l = (const float*)p; else bg = (const float*)p; break;
            default: break;
        }
    }

    float* out = (float*)d_out;
    const int n = 50000;
    const int E = 800000;

    int eb = (E + 255) / 256;
    int gb = (n + 31) / 32;
    int wb = (n * 32 + 255) / 256;

    // CSR build (int atomics only)
    init_kernel<<<(n + 255) / 256, 256>>>(n);
    probe_kernel<<<1, 32>>>(idx);
    decode_kernel<<<eb, 256>>>(idx, E);
    scan_kernel<<<1, 1024>>>(n, E);
    fill_kernel<<<eb, 256>>>(E);

    // Layer 1: SAGE(x)
    gather_kernel<true><<<wb, 256>>>(x, n);
    sage_gemm_kernel<1><<<gb, 256>>>(x, W1l, b1l, W1r, n);

    // Layer 2: SAGE(h1)
    gather_kernel<false><<<wb, 256>>>(nullptr, n);
    sage_gemm_kernel<2><<<gb, 256>>>(nullptr, W2l, b2l, W2r, n);

    // softmax + GCN
    softmax_gcn_kernel<<<(n + 7) / 8, 256>>>(Wg, bg, out, n);
    gcn_gather_kernel<<<wb, 256>>>(out, n);
}

// round 12
// speedup vs baseline: 1.1694x; 1.1694x over previous
#include <cuda_runtime.h>
#include <cuda_bf16.h>
#include <math.h>

// Problem constants
#define MAXN 50000
#define MAXE 800000
#define F1   128   // F_IN and H
#define F2   64    // C
#define NB_SCAN ((MAXN + 255) / 256)     // 196 scan blocks

// ---------------- scratch (__device__ globals; no allocs allowed) --------------
__device__ __align__(16) float g_agg[MAXN * F1];   // agg1 (128w) / t2l+t2r (64w each)
__device__ __align__(16) float g_h1 [MAXN * F1];   // SAGE1 output
__device__ __align__(16) float g_y  [MAXN * F2];   // softmax(h2)@Wg * dinv[src]
__device__ __align__(16) float g_dinv[MAXN];       // rsqrt(indeg+1)
__device__ __align__(16) int2  g_edge[MAXE];       // packed (src,dst)
__device__ __align__(16) int   g_csrc[MAXE];       // CSR: src ids grouped by dst
__device__ __align__(16) int   g_cnt [MAXN];       // in-degree (int)
__device__ __align__(16) int   g_rowptr[MAXN + 1];
__device__ __align__(16) int   g_cursor[MAXN];
__device__ __align__(16) int   g_bsum[NB_SCAN];
__device__ __align__(16) int   g_boff[NB_SCAN];
__device__ int g_isi64;

// ---------------- init ---------------------------------------------------------
__global__ void init_kernel(int n) {
    int i = blockIdx.x * blockDim.x + threadIdx.x;
    if (i < n) g_cnt[i] = 0;
}

// ---------------- probe: is edge_index int64 or int32? -------------------------
__global__ void probe_kernel(const void* __restrict__ idxv) {
    if (threadIdx.x == 0 && blockIdx.x == 0) {
        const long long* p = (const long long*)idxv;
        int ok = 1;
        for (int i = 0; i < 64; i++) {
            long long v = p[i];
            if (v < 0 || v >= 2147483648LL) { ok = 0; break; }
        }
        g_isi64 = ok;
    }
}

// ---------------- decode: edge_index -> int2, degree count ---------------------
__global__ void decode_kernel(const void* __restrict__ idxv, int E) {
    int e = blockIdx.x * blockDim.x + threadIdx.x;
    if (e >= E) return;
    int s, d;
    if (g_isi64) {
        const long long* p = (const long long*)idxv;
        s = (int)p[e];
        d = (int)p[E + e];
    } else {
        const int* p = (const int*)idxv;
        s = p[e];
        d = p[E + e];
    }
    g_edge[e] = make_int2(s, d);
    atomicAdd(&g_cnt[d], 1);
}

// ---------------- 3-phase multi-block exclusive scan ---------------------------
__device__ __forceinline__ int block_scan256(int v, int* wsum, int lane, int wid,
                                             int* block_total) {
    int x = v;
#pragma unroll
    for (int o = 1; o < 32; o <<= 1) {
        int t = __shfl_up_sync(0xffffffffu, x, o);
        if (lane >= o) x += t;
    }
    if (lane == 31) wsum[wid] = x;
    __syncthreads();
    if (wid == 0 && lane < 8) {
        int y = wsum[lane];
#pragma unroll
        for (int o = 1; o < 8; o <<= 1) {
            int t = __shfl_up_sync(0x000000ffu, y, o);
            if (lane >= o) y += t;
        }
        wsum[lane] = y;
    }
    __syncthreads();
    *block_total = wsum[7];
    return (wid ? wsum[wid - 1] : 0) + x - v;   // exclusive within block
}

__global__ void __launch_bounds__(256) scanA_kernel(int n) {
    __shared__ int wsum[8];
    int tid = threadIdx.x, lane = tid & 31, wid = tid >> 5;
    int i = blockIdx.x * 256 + tid;
    int v = (i < n) ? g_cnt[i] : 0;
    int total;
    int excl = block_scan256(v, wsum, lane, wid, &total);
    if (i < n) g_rowptr[i] = excl;
    if (tid == 0) g_bsum[blockIdx.x] = total;
}

__global__ void __launch_bounds__(256) scanB_kernel(int nb) {
    __shared__ int wsum[8];
    int tid = threadIdx.x, lane = tid & 31, wid = tid >> 5;
    int v = (tid < nb) ? g_bsum[tid] : 0;
    int total;
    int excl = block_scan256(v, wsum, lane, wid, &total);
    if (tid < nb) g_boff[tid] = excl;
}

__global__ void __launch_bounds__(256) scanC_kernel(int n, int E) {
    int i = blockIdx.x * 256 + threadIdx.x;
    if (i < n) {
        int v = g_rowptr[i] + g_boff[i >> 8];
        g_rowptr[i] = v;
        g_cursor[i] = v;
    }
    if (i == 0) g_rowptr[n] = E;
}

// ---------------- CSR fill ------------------------------------------------------
__global__ void fill_kernel(int E) {
    int e = blockIdx.x * blockDim.x + threadIdx.x;
    if (e >= E) return;
    int2 ed = g_edge[e];
    int pos = atomicAdd(&g_cursor[ed.y], 1);
    g_csrc[pos] = ed.x;
}

// ---------------- SAGE1 mean-aggregation gather (warp per node, 128-wide) ------
__global__ void __launch_bounds__(256)
gather1_kernel(const float* __restrict__ feat, int n) {
    int w = (blockIdx.x * blockDim.x + threadIdx.x) >> 5;
    if (w >= n) return;
    int lane = threadIdx.x & 31;

    int beg = g_rowptr[w], end = g_rowptr[w + 1];
    float4 acc = make_float4(0.f, 0.f, 0.f, 0.f);
    for (int chunk = beg; chunk < end; chunk += 32) {
        int myidx = (chunk + lane < end) ? g_csrc[chunk + lane] : 0;
        int m = min(32, end - chunk);
        int j = 0;
        for (; j + 4 <= m; j += 4) {
            int s0 = __shfl_sync(0xffffffffu, myidx, j);
            int s1 = __shfl_sync(0xffffffffu, myidx, j + 1);
            int s2 = __shfl_sync(0xffffffffu, myidx, j + 2);
            int s3 = __shfl_sync(0xffffffffu, myidx, j + 3);
            float4 v0 = *reinterpret_cast<const float4*>(feat + (size_t)s0 * F1 + lane * 4);
            float4 v1 = *reinterpret_cast<const float4*>(feat + (size_t)s1 * F1 + lane * 4);
            float4 v2 = *reinterpret_cast<const float4*>(feat + (size_t)s2 * F1 + lane * 4);
            float4 v3 = *reinterpret_cast<const float4*>(feat + (size_t)s3 * F1 + lane * 4);
            acc.x += v0.x + v1.x + v2.x + v3.x;
            acc.y += v0.y + v1.y + v2.y + v3.y;
            acc.z += v0.z + v1.z + v2.z + v3.z;
            acc.w += v0.w + v1.w + v2.w + v3.w;
        }
        for (; j < m; j++) {
            int s = __shfl_sync(0xffffffffu, myidx, j);
            float4 v = *reinterpret_cast<const float4*>(feat + (size_t)s * F1 + lane * 4);
            acc.x += v.x; acc.y += v.y; acc.z += v.z; acc.w += v.w;
        }
    }
    float r = 1.f / fmaxf((float)(end - beg), 1.f);
    acc.x *= r; acc.y *= r; acc.z *= r; acc.w *= r;
    *reinterpret_cast<float4*>(g_agg + (size_t)w * F1 + lane * 4) = acc;
}

// ---------------- SAGE1 GEMM: h1 = relu(agg@W1l + b1l + x@W1r) -----------------
__global__ void __launch_bounds__(256)
sage1_gemm_kernel(const float* __restrict__ x,
                  const float* __restrict__ Wl,
                  const float* __restrict__ bl,
                  const float* __restrict__ Wr, int n) {
    constexpr int FIN = 128, FOUT = 128, TM = 32, KT = 32, HV = 4;

    __shared__ __align__(16) float sWl[KT][FOUT];
    __shared__ __align__(16) float sWr[KT][FOUT];
    __shared__ __align__(16) float sM[TM][KT];
    __shared__ __align__(16) float sX[TM][KT];

    int tid = threadIdx.x;
    int tx = tid & 31;
    int ty = tid >> 5;
    int nbase = blockIdx.x * TM;

    float acc[4][HV];
#pragma unroll
    for (int m = 0; m < 4; m++)
#pragma unroll
        for (int j = 0; j < HV; j++) acc[m][j] = 0.f;

    for (int kt = 0; kt < FIN; kt += KT) {
#pragma unroll
        for (int i = tid; i < KT * FOUT / 4; i += 256) {
            int k = i / (FOUT / 4);
            int h = (i % (FOUT / 4)) * 4;
            *reinterpret_cast<float4*>(&sWl[k][h]) =
                *reinterpret_cast<const float4*>(&Wl[(size_t)(kt + k) * FOUT + h]);
            *reinterpret_cast<float4*>(&sWr[k][h]) =
                *reinterpret_cast<const float4*>(&Wr[(size_t)(kt + k) * FOUT + h]);
        }
        {
            int nl = tid / (KT / 4);
            int k  = (tid % (KT / 4)) * 4;
            int node = nbase + nl;
            float4 a = make_float4(0.f, 0.f, 0.f, 0.f);
            float4 xx = a;
            if (node < n) {
                a  = *reinterpret_cast<const float4*>(&g_agg[(size_t)node * FIN + kt + k]);
                xx = *reinterpret_cast<const float4*>(&x    [(size_t)node * FIN + kt + k]);
            }
            *reinterpret_cast<float4*>(&sM[nl][k]) = a;
            *reinterpret_cast<float4*>(&sX[nl][k]) = xx;
        }
        __syncthreads();

#pragma unroll
        for (int k = 0; k < KT; k++) {
            float4 t1 = *reinterpret_cast<const float4*>(&sWl[k][tx * 4]);
            float4 t2 = *reinterpret_cast<const float4*>(&sWr[k][tx * 4]);
            float wl[4] = {t1.x, t1.y, t1.z, t1.w};
            float wr[4] = {t2.x, t2.y, t2.z, t2.w};
            float rm[4], rx[4];
#pragma unroll
            for (int m = 0; m < 4; m++) {
                rm[m] = sM[ty * 4 + m][k];
                rx[m] = sX[ty * 4 + m][k];
            }
#pragma unroll
            for (int m = 0; m < 4; m++)
#pragma unroll
                for (int j = 0; j < 4; j++)
                    acc[m][j] += rm[m] * wl[j] + rx[m] * wr[j];
        }
        __syncthreads();
    }

#pragma unroll
    for (int m = 0; m < 4; m++) {
        int node = nbase + ty * 4 + m;
        if (node < n) {
#pragma unroll
            for (int j = 0; j < 4; j++) {
                float o = fmaxf(acc[m][j] + bl[tx * 4 + j], 0.f);
                g_h1[(size_t)node * FOUT + tx * 4 + j] = o;
            }
        }
    }
}

// ---------------- SAGE2 dual GEMM: t2l = h1@W2l ; t2r = h1@W2r + b2l -----------
// (transform-before-gather: mean(h1_j)@W2l == mean(h1_j@W2l))
__global__ void __launch_bounds__(256)
sage2_gemm_kernel(const float* __restrict__ Wl,
                  const float* __restrict__ bl,
                  const float* __restrict__ Wr, int n) {
    constexpr int FIN = 128, FOUT = 64, TM = 32, KT = 32;
    float* __restrict__ t2l = g_agg;
    float* __restrict__ t2r = g_agg + (size_t)MAXN * F2;

    __shared__ __align__(16) float sWl[KT][FOUT];
    __shared__ __align__(16) float sWr[KT][FOUT];
    __shared__ __align__(16) float sH[TM][KT];

    int tid = threadIdx.x;
    int tx = tid & 31;
    int ty = tid >> 5;
    int nbase = blockIdx.x * TM;

    float accl[4][2], accr[4][2];
#pragma unroll
    for (int m = 0; m < 4; m++) {
        accl[m][0] = accl[m][1] = 0.f;
        accr[m][0] = accr[m][1] = 0.f;
    }

    for (int kt = 0; kt < FIN; kt += KT) {
#pragma unroll
        for (int i = tid; i < KT * FOUT / 4; i += 256) {
            int k = i / (FOUT / 4);
            int h = (i % (FOUT / 4)) * 4;
            *reinterpret_cast<float4*>(&sWl[k][h]) =
                *reinterpret_cast<const float4*>(&Wl[(size_t)(kt + k) * FOUT + h]);
            *reinterpret_cast<float4*>(&sWr[k][h]) =
                *reinterpret_cast<const float4*>(&Wr[(size_t)(kt + k) * FOUT + h]);
        }
        {
            int nl = tid / (KT / 4);
            int k  = (tid % (KT / 4)) * 4;
            int node = nbase + nl;
            float4 h = make_float4(0.f, 0.f, 0.f, 0.f);
            if (node < n)
                h = *reinterpret_cast<const float4*>(&g_h1[(size_t)node * FIN + kt + k]);
            *reinterpret_cast<float4*>(&sH[nl][k]) = h;
        }
        __syncthreads();

#pragma unroll
        for (int k = 0; k < KT; k++) {
            float2 t1 = *reinterpret_cast<const float2*>(&sWl[k][tx * 2]);
            float2 t2 = *reinterpret_cast<const float2*>(&sWr[k][tx * 2]);
            float rh[4];
#pragma unroll
            for (int m = 0; m < 4; m++) rh[m] = sH[ty * 4 + m][k];
#pragma unroll
            for (int m = 0; m < 4; m++) {
                accl[m][0] += rh[m] * t1.x;
                accl[m][1] += rh[m] * t1.y;
                accr[m][0] += rh[m] * t2.x;
                accr[m][1] += rh[m] * t2.y;
            }
        }
        __syncthreads();
    }

#pragma unroll
    for (int m = 0; m < 4; m++) {
        int node = nbase + ty * 4 + m;
        if (node < n) {
            t2l[(size_t)node * FOUT + tx * 2]     = accl[m][0];
            t2l[(size_t)node * FOUT + tx * 2 + 1] = accl[m][1];
            t2r[(size_t)node * FOUT + tx * 2]     = accr[m][0] + bl[tx * 2];
            t2r[(size_t)node * FOUT + tx * 2 + 1] = accr[m][1] + bl[tx * 2 + 1];
        }
    }
}

// ---------------- fused gather2 + softmax + Wg GEMM + out init -----------------
// h2 = mean-gather(t2l) + t2r; s = softmax(h2); a = s@Wg; di = rsqrt(deg+1)
// y = a*di; out = a*di*di + bg
__global__ void __launch_bounds__(256)
sage2_post_kernel(const float* __restrict__ Wg, const float* __restrict__ bg,
                  float* __restrict__ out, int n) {
    const float* __restrict__ t2l = g_agg;
    const float* __restrict__ t2r = g_agg + (size_t)MAXN * F2;
    __shared__ __align__(16) float sW[F2 * F2];
    __shared__ float sB[F2];
    __shared__ float sS[8][F2];
    int tid = threadIdx.x;
#pragma unroll
    for (int i = tid; i < F2 * F2 / 4; i += 256)
        reinterpret_cast<float4*>(sW)[i] = reinterpret_cast<const float4*>(Wg)[i];
    if (tid < F2) sB[tid] = bg[tid];
    __syncthreads();

    int warp = tid >> 5, lane = tid & 31;
    int node = blockIdx.x * 8 + warp;
    if (node >= n) return;

    int beg = g_rowptr[node], end = g_rowptr[node + 1];
    float2 acc = make_float2(0.f, 0.f);
    for (int chunk = beg; chunk < end; chunk += 32) {
        int myidx = (chunk + lane < end) ? g_csrc[chunk + lane] : 0;
        int m = min(32, end - chunk);
        int j = 0;
        for (; j + 4 <= m; j += 4) {
            int s0 = __shfl_sync(0xffffffffu, myidx, j);
            int s1 = __shfl_sync(0xffffffffu, myidx, j + 1);
            int s2 = __shfl_sync(0xffffffffu, myidx, j + 2);
            int s3 = __shfl_sync(0xffffffffu, myidx, j + 3);
            float2 v0 = *reinterpret_cast<const float2*>(t2l + (size_t)s0 * F2 + lane * 2);
            float2 v1 = *reinterpret_cast<const float2*>(t2l + (size_t)s1 * F2 + lane * 2);
            float2 v2 = *reinterpret_cast<const float2*>(t2l + (size_t)s2 * F2 + lane * 2);
            float2 v3 = *reinterpret_cast<const float2*>(t2l + (size_t)s3 * F2 + lane * 2);
            acc.x += v0.x + v1.x + v2.x + v3.x;
            acc.y += v0.y + v1.y + v2.y + v3.y;
        }
        for (; j < m; j++) {
            int s = __shfl_sync(0xffffffffu, myidx, j);
            float2 v = *reinterpret_cast<const float2*>(t2l + (size_t)s * F2 + lane * 2);
            acc.x += v.x; acc.y += v.y;
        }
    }
    int deg = end - beg;
    float r = 1.f / fmaxf((float)deg, 1.f);
    float2 tr = *reinterpret_cast<const float2*>(t2r + (size_t)node * F2 + lane * 2);
    float h0 = acc.x * r + tr.x;
    float h1 = acc.y * r + tr.y;

    // softmax over 64 values (2 per lane)
    float mx = fmaxf(h0, h1);
#pragma unroll
    for (int o = 16; o; o >>= 1) mx = fmaxf(mx, __shfl_xor_sync(0xffffffffu, mx, o));
    float e0 = __expf(h0 - mx), e1 = __expf(h1 - mx);
    float sm = e0 + e1;
#pragma unroll
    for (int o = 16; o; o >>= 1) sm += __shfl_xor_sync(0xffffffffu, sm, o);
    float inv = 1.f / sm;
    sS[warp][lane * 2]     = e0 * inv;
    sS[warp][lane * 2 + 1] = e1 * inv;
    __syncwarp();

    float a0 = 0.f, a1 = 0.f;
#pragma unroll
    for (int k = 0; k < F2; k++) {
        float s = sS[warp][k];
        a0 += s * sW[k * F2 + lane];
        a1 += s * sW[k * F2 + lane + 32];
    }
    float di = rsqrtf((float)deg + 1.0f);     // deg + self loop
    float y0 = a0 * di, y1 = a1 * di;
    g_y[(size_t)node * F2 + lane]      = y0;
    g_y[(size_t)node * F2 + lane + 32] = y1;
    if (lane == 0) g_dinv[node] = di;
    out[(size_t)node * F2 + lane]      = y0 * di + sB[lane];
    out[(size_t)node * F2 + lane + 32] = y1 * di + sB[lane + 32];
}

// ---------------- GCN gather: out[i] += dinv[i] * sum_{s in N(i)} y[s] ---------
__global__ void __launch_bounds__(256)
gcn_gather_kernel(float* __restrict__ out, int n) {
    int w = (blockIdx.x * blockDim.x + threadIdx.x) >> 5;
    if (w >= n) return;
    int lane = threadIdx.x & 31;

    int beg = g_rowptr[w], end = g_rowptr[w + 1];
    float2 acc = make_float2(0.f, 0.f);
    for (int chunk = beg; chunk < end; chunk += 32) {
        int myidx = (chunk + lane < end) ? g_csrc[chunk + lane] : 0;
        int m = min(32, end - chunk);
        int j = 0;
        for (; j + 4 <= m; j += 4) {
            int s0 = __shfl_sync(0xffffffffu, myidx, j);
            int s1 = __shfl_sync(0xffffffffu, myidx, j + 1);
            int s2 = __shfl_sync(0xffffffffu, myidx, j + 2);
            int s3 = __shfl_sync(0xffffffffu, myidx, j + 3);
            float2 v0 = *reinterpret_cast<const float2*>(g_y + (size_t)s0 * F2 + lane * 2);
            float2 v1 = *reinterpret_cast<const float2*>(g_y + (size_t)s1 * F2 + lane * 2);
            float2 v2 = *reinterpret_cast<const float2*>(g_y + (size_t)s2 * F2 + lane * 2);
            float2 v3 = *reinterpret_cast<const float2*>(g_y + (size_t)s3 * F2 + lane * 2);
            acc.x += v0.x + v1.x + v2.x + v3.x;
            acc.y += v0.y + v1.y + v2.y + v3.y;
        }
        for (; j < m; j++) {
            int s = __shfl_sync(0xffffffffu, myidx, j);
            float2 v = *reinterpret_cast<const float2*>(g_y + (size_t)s * F2 + lane * 2);
            acc.x += v.x; acc.y += v.y;
        }
    }
    float di = g_dinv[w];
    float* o = out + (size_t)w * F2 + lane * 2;
    o[0] += di * acc.x;
    o[1] += di * acc.y;
}

// ---------------- launch -------------------------------------------------------
extern "C" void kernel_launch(void* const* d_in, const int* in_sizes, int n_in,
                              void* d_out, int out_size) {
    const float* x   = nullptr;
    const void*  idx = nullptr;
    const float *W1l = nullptr, *W1r = nullptr, *b1l = nullptr;
    const float *W2l = nullptr, *W2r = nullptr, *b2l = nullptr;
    const float *Wg  = nullptr, *bg  = nullptr;

    for (int i = 0; i < n_in; i++) {
        int sz = in_sizes[i];
        const void* p = d_in[i];
        switch (sz) {
            case 6400000: x = (const float*)p; break;
            case 1600000: idx = p; break;
            case 16384:  if (!W1l) W1l = (const float*)p; else W1r = (const float*)p; break;
            case 8192:   if (!W2l) W2l = (const float*)p; else W2r = (const float*)p; break;
            case 4096:   Wg = (const float*)p; break;
            case 128:    b1l = (const float*)p; break;
            case 64:     if (!b2l) b2l = (const float*)p; else bg = (const float*)p; break;
            default: break;
        }
    }

    float* out = (float*)d_out;
    const int n = 50000;
    const int E = 800000;

    int eb = (E + 255) / 256;
    int gb = (n + 31) / 32;
    int wb = (n * 32 + 255) / 256;
    int nb = (n + 255) / 256;

    // CSR build
    init_kernel<<<nb, 256>>>(n);
    probe_kernel<<<1, 32>>>(idx);
    decode_kernel<<<eb, 256>>>(idx, E);
    scanA_kernel<<<nb, 256>>>(n);
    scanB_kernel<<<1, 256>>>(nb);
    scanC_kernel<<<nb, 256>>>(n, E);
    fill_kernel<<<eb, 256>>>(E);

    // Layer 1: SAGE(x)
    gather1_kernel<<<wb, 256>>>(x, n);
    sage1_gemm_kernel<<<gb, 256>>>(x, W1l, b1l, W1r, n);

    // Layer 2: transform first, then 64-wide gather fused with softmax+Wg
    sage2_gemm_kernel<<<gb, 256>>>(W2l, b2l, W2r, n);
    sage2_post_kernel<<<(n + 7) / 8, 256>>>(Wg, bg, out, n);

    // GCN neighbor term
    gcn_gather_kernel<<<wb, 256>>>(out, n);
}

// round 14
// speedup vs baseline: 1.5085x; 1.2900x over previous
#include <cuda_runtime.h>
#include <cuda_bf16.h>
#include <math.h>
#include <stdint.h>

// Problem constants
#define MAXN 50000
#define MAXE 800000
#define F1   128   // F_IN and H
#define F2   64    // C

// ---------------- scratch (__device__ globals; no allocs allowed) --------------
// A1 layout per node (512 bf16): [agg_hi(128) | agg_lo(128) | x_hi(128) | x_lo(128)]
// A2 layout per node (256 bf16): [h1_hi(128) | h1_lo(128)]
__device__ __align__(16) __nv_bfloat16 g_A1[(size_t)MAXN * 512];
__device__ __align__(16) __nv_bfloat16 g_A2[(size_t)MAXN * 256];
__device__ __align__(16) __nv_bfloat16 g_W1[768 * 128];  // blocked split W for layer1
__device__ __align__(16) __nv_bfloat16 g_W2[384 * 128];  // blocked split W for layer2
__device__ __align__(16) float g_t2l[(size_t)MAXN * F2];
__device__ __align__(16) float g_t2r[(size_t)MAXN * F2];
__device__ __align__(16) float g_y  [(size_t)MAXN * F2];
__device__ __align__(16) float g_dinv[MAXN];
__device__ __align__(16) int2  g_edge[MAXE];
__device__ __align__(16) int   g_csrc[MAXE];
__device__ __align__(16) int   g_cnt [MAXN];
__device__ __align__(16) int   g_rowptr[MAXN + 1];
__device__ __align__(16) int   g_cursor[MAXN];
#define NB_SCAN ((MAXN + 255) / 256)
__device__ __align__(16) int   g_bsum[NB_SCAN];
__device__ __align__(16) int   g_boff[NB_SCAN];
__device__ int g_isi64;

// ---------------- mma helpers ---------------------------------------------------
__device__ __forceinline__ uint32_t smem_u32(const void* p) {
    return (uint32_t)__cvta_generic_to_shared(p);
}
__device__ __forceinline__ void ldsm_x4(uint32_t* r, uint32_t a) {
    asm volatile("ldmatrix.sync.aligned.m8n8.x4.shared.b16 {%0,%1,%2,%3}, [%4];"
        : "=r"(r[0]), "=r"(r[1]), "=r"(r[2]), "=r"(r[3]) : "r"(a));
}
__device__ __forceinline__ void ldsm_x4_t(uint32_t* r, uint32_t a) {
    asm volatile("ldmatrix.sync.aligned.m8n8.x4.trans.shared.b16 {%0,%1,%2,%3}, [%4];"
        : "=r"(r[0]), "=r"(r[1]), "=r"(r[2]), "=r"(r[3]) : "r"(a));
}
__device__ __forceinline__ void mma16816(float* d, const uint32_t* a,
                                         uint32_t b0, uint32_t b1) {
    asm volatile("mma.sync.aligned.m16n8k16.row.col.f32.bf16.bf16.f32 "
        "{%0,%1,%2,%3}, {%4,%5,%6,%7}, {%8,%9}, {%0,%1,%2,%3};"
        : "+f"(d[0]), "+f"(d[1]), "+f"(d[2]), "+f"(d[3])
        : "r"(a[0]), "r"(a[1]), "r"(a[2]), "r"(a[3]), "r"(b0), "r"(b1));
}
__device__ __forceinline__ void split_bf16(float v, __nv_bfloat16& hi, __nv_bfloat16& lo) {
    hi = __float2bfloat16(v);
    lo = __float2bfloat16(v - __bfloat162float(hi));
}

// ---------------- init ---------------------------------------------------------
__global__ void init_kernel(int n) {
    int i = blockIdx.x * blockDim.x + threadIdx.x;
    if (i < n) g_cnt[i] = 0;
}

// ---------------- probe: is edge_index int64 or int32? -------------------------
__global__ void probe_kernel(const void* __restrict__ idxv) {
    if (threadIdx.x == 0 && blockIdx.x == 0) {
        const long long* p = (const long long*)idxv;
        int ok = 1;
        for (int i = 0; i < 64; i++) {
            long long v = p[i];
            if (v < 0 || v >= 2147483648LL) { ok = 0; break; }
        }
        g_isi64 = ok;
    }
}

// ---------------- decode -------------------------------------------------------
__global__ void decode_kernel(const void* __restrict__ idxv, int E) {
    int e = blockIdx.x * blockDim.x + threadIdx.x;
    if (e >= E) return;
    int s, d;
    if (g_isi64) {
        const long long* p = (const long long*)idxv;
        s = (int)p[e];
        d = (int)p[E + e];
    } else {
        const int* p = (const int*)idxv;
        s = p[e];
        d = p[E + e];
    }
    g_edge[e] = make_int2(s, d);
    atomicAdd(&g_cnt[d], 1);
}

// ---------------- 3-phase multi-block exclusive scan ---------------------------
__device__ __forceinline__ int block_scan256(int v, int* wsum, int lane, int wid,
                                             int* block_total) {
    int x = v;
#pragma unroll
    for (int o = 1; o < 32; o <<= 1) {
        int t = __shfl_up_sync(0xffffffffu, x, o);
        if (lane >= o) x += t;
    }
    if (lane == 31) wsum[wid] = x;
    __syncthreads();
    if (wid == 0 && lane < 8) {
        int y = wsum[lane];
#pragma unroll
        for (int o = 1; o < 8; o <<= 1) {
            int t = __shfl_up_sync(0x000000ffu, y, o);
            if (lane >= o) y += t;
        }
        wsum[lane] = y;
    }
    __syncthreads();
    *block_total = wsum[7];
    return (wid ? wsum[wid - 1] : 0) + x - v;
}

__global__ void __launch_bounds__(256) scanA_kernel(int n) {
    __shared__ int wsum[8];
    int tid = threadIdx.x, lane = tid & 31, wid = tid >> 5;
    int i = blockIdx.x * 256 + tid;
    int v = (i < n) ? g_cnt[i] : 0;
    int total;
    int excl = block_scan256(v, wsum, lane, wid, &total);
    if (i < n) g_rowptr[i] = excl;
    if (tid == 0) g_bsum[blockIdx.x] = total;
}

__global__ void __launch_bounds__(256) scanB_kernel(int nb) {
    __shared__ int wsum[8];
    int tid = threadIdx.x, lane = tid & 31, wid = tid >> 5;
    int v = (tid < nb) ? g_bsum[tid] : 0;
    int total;
    int excl = block_scan256(v, wsum, lane, wid, &total);
    if (tid < nb) g_boff[tid] = excl;
}

__global__ void __launch_bounds__(256) scanC_kernel(int n, int E) {
    int i = blockIdx.x * 256 + threadIdx.x;
    if (i < n) {
        int v = g_rowptr[i] + g_boff[i >> 8];
        g_rowptr[i] = v;
        g_cursor[i] = v;
    }
    if (i == 0) g_rowptr[n] = E;
}

// ---------------- CSR fill ------------------------------------------------------
__global__ void fill_kernel(int E) {
    int e = blockIdx.x * blockDim.x + threadIdx.x;
    if (e >= E) return;
    int2 ed = g_edge[e];
    int pos = atomicAdd(&g_cursor[ed.y], 1);
    g_csrc[pos] = ed.x;
}

// ---------------- convert x -> bf16 hi/lo panels of A1 -------------------------
__global__ void convx_kernel(const float* __restrict__ x, int n) {
    int i = blockIdx.x * blockDim.x + threadIdx.x;    // n*64 threads (2 cols each)
    if (i >= n * 64) return;
    int node = i >> 6;
    int c = (i & 63) * 2;
    float2 v = *reinterpret_cast<const float2*>(x + (size_t)node * F1 + c);
    __nv_bfloat16 h0, l0, h1, l1;
    split_bf16(v.x, h0, l0);
    split_bf16(v.y, h1, l1);
    __nv_bfloat162 hp; hp.x = h0; hp.y = h1;
    __nv_bfloat162 lp; lp.x = l0; lp.y = l1;
    *reinterpret_cast<__nv_bfloat162*>(&g_A1[(size_t)node * 512 + 256 + c]) = hp;
    *reinterpret_cast<__nv_bfloat162*>(&g_A1[(size_t)node * 512 + 384 + c]) = lp;
}

// ---------------- weight prep: blocked split weights ---------------------------
// W1 blocks (rows b*128+rr): b0,b1: W1l_hi; b2: W1l_lo; b3,b4: W1r_hi; b5: W1r_lo
// W2 blocks: Wcat=[W2l|W2r];  b0,b1: Wcat_hi; b2: Wcat_lo
__global__ void convw_kernel(const float* __restrict__ W1l, const float* __restrict__ W1r,
                             const float* __restrict__ W2l, const float* __restrict__ W2r) {
    int i = blockIdx.x * blockDim.x + threadIdx.x;    // 98304 + 49152 = 147456
    if (i < 98304) {
        int r = i >> 7, c = i & 127;
        int b = r >> 7, rr = r & 127;
        float v = (b < 3) ? W1l[rr * 128 + c] : W1r[rr * 128 + c];
        __nv_bfloat16 hi, lo;
        split_bf16(v, hi, lo);
        g_W1[i] = (b == 2 || b == 5) ? lo : hi;
    } else if (i < 147456) {
        int i2 = i - 98304;
        int r = i2 >> 7, c = i2 & 127;
        int b = r >> 7, rr = r & 127;
        float v = (c < 64) ? W2l[rr * 64 + c] : W2r[rr * 64 + (c - 64)];
        __nv_bfloat16 hi, lo;
        split_bf16(v, hi, lo);
        g_W2[i2] = (b == 2) ? lo : hi;
    }
}

// ---------------- SAGE1 gather -> mean -> bf16 split into A1 -------------------
__global__ void __launch_bounds__(256)
gather1_kernel(const float* __restrict__ feat, int n) {
    int w = (blockIdx.x * blockDim.x + threadIdx.x) >> 5;
    if (w >= n) return;
    int lane = threadIdx.x & 31;

    int beg = g_rowptr[w], end = g_rowptr[w + 1];
    float4 acc = make_float4(0.f, 0.f, 0.f, 0.f);
    for (int chunk = beg; chunk < end; chunk += 32) {
        int myidx = (chunk + lane < end) ? g_csrc[chunk + lane] : 0;
        int m = min(32, end - chunk);
        int j = 0;
        for (; j + 4 <= m; j += 4) {
            int s0 = __shfl_sync(0xffffffffu, myidx, j);
            int s1 = __shfl_sync(0xffffffffu, myidx, j + 1);
            int s2 = __shfl_sync(0xffffffffu, myidx, j + 2);
            int s3 = __shfl_sync(0xffffffffu, myidx, j + 3);
            float4 v0 = *reinterpret_cast<const float4*>(feat + (size_t)s0 * F1 + lane * 4);
            float4 v1 = *reinterpret_cast<const float4*>(feat + (size_t)s1 * F1 + lane * 4);
            float4 v2 = *reinterpret_cast<const float4*>(feat + (size_t)s2 * F1 + lane * 4);
            float4 v3 = *reinterpret_cast<const float4*>(feat + (size_t)s3 * F1 + lane * 4);
            acc.x += v0.x + v1.x + v2.x + v3.x;
            acc.y += v0.y + v1.y + v2.y + v3.y;
            acc.z += v0.z + v1.z + v2.z + v3.z;
            acc.w += v0.w + v1.w + v2.w + v3.w;
        }
        for (; j < m; j++) {
            int s = __shfl_sync(0xffffffffu, myidx, j);
            float4 v = *reinterpret_cast<const float4*>(feat + (size_t)s * F1 + lane * 4);
            acc.x += v.x; acc.y += v.y; acc.z += v.z; acc.w += v.w;
        }
    }
    float r = 1.f / fmaxf((float)(end - beg), 1.f);
    float v[4] = {acc.x * r, acc.y * r, acc.z * r, acc.w * r};
    __nv_bfloat16 h[4], l[4];
#pragma unroll
    for (int j = 0; j < 4; j++) split_bf16(v[j], h[j], l[j]);
    __nv_bfloat162 hp0; hp0.x = h[0]; hp0.y = h[1];
    __nv_bfloat162 hp1; hp1.x = h[2]; hp1.y = h[3];
    __nv_bfloat162 lp0; lp0.x = l[0]; lp0.y = l[1];
    __nv_bfloat162 lp1; lp1.x = l[2]; lp1.y = l[3];
    size_t base = (size_t)w * 512 + lane * 4;
    *reinterpret_cast<__nv_bfloat162*>(&g_A1[base])           = hp0;
    *reinterpret_cast<__nv_bfloat162*>(&g_A1[base + 2])       = hp1;
    *reinterpret_cast<__nv_bfloat162*>(&g_A1[base + 128])     = lp0;
    *reinterpret_cast<__nv_bfloat162*>(&g_A1[base + 130])     = lp1;
}

// ---------------- HMMA GEMM: C[128-row tile][128] = A(blocked bf16) @ Wb -------
// All operand arrays are selected INSIDE device code from the template param
// (passing __device__ symbols as host-side kernel args reads the host shadow
// symbol — silently wrong on GB300 because ATS makes host RAM readable).
// L==1: C = relu(... + b1l) -> split into A2 panels
// L==2: C cols 0-63 -> t2l ; cols 64-127 -> t2r (+ b2l)
template <int KCHUNKS, int L>
__global__ void __launch_bounds__(256)
mma_gemm_kernel(const float* __restrict__ bias, int n) {
    const __nv_bfloat16* __restrict__ A  = (L == 1) ? g_A1 : g_A2;
    const __nv_bfloat16* __restrict__ Wb = (L == 1) ? g_W1 : g_W2;
    const int astride = (L == 1) ? 512 : 256;

    __shared__ __align__(16) __nv_bfloat16 sA[128 * 40];   // 128 rows x 32 k (pad 8)
    __shared__ __align__(16) __nv_bfloat16 sW[32 * 136];   // 32 k x 128 n (pad 8)

    int tid = threadIdx.x;
    int wid = tid >> 5, lane = tid & 31;
    int rw = wid & 3;          // row-warp: rows rw*32 .. +32
    int cw = wid >> 2;         // col-warp: cols cw*64 .. +64
    int nbase = blockIdx.x * 128;

    float acc[2][8][4];
#pragma unroll
    for (int a = 0; a < 2; a++)
#pragma unroll
        for (int b = 0; b < 8; b++)
#pragma unroll
            for (int c = 0; c < 4; c++) acc[a][b][c] = 0.f;

    for (int ch = 0; ch < KCHUNKS; ch++) {
        int blk = ch >> 2;
        int aoff;
        if (L == 1) {
            const int lut[6] = {0, 128, 0, 256, 384, 256};
            aoff = lut[blk] + (ch & 3) * 32;
        } else {
            const int lut[3] = {0, 128, 0};
            aoff = lut[blk] + (ch & 3) * 32;
        }
        // stage A tile (128 x 32 bf16)
        {
            int idx = tid;
#pragma unroll
            for (int it = 0; it < 2; it++, idx += 256) {
                int row = idx >> 2, q = (idx & 3) * 8;
                int node = nbase + row;
                int4 v = make_int4(0, 0, 0, 0);
                if (node < n)
                    v = *reinterpret_cast<const int4*>(A + (size_t)node * astride + aoff + q);
                *reinterpret_cast<int4*>(&sA[row * 40 + q]) = v;
            }
        }
        // stage W tile (32 x 128 bf16)
        {
            int idx = tid;
#pragma unroll
            for (int it = 0; it < 2; it++, idx += 256) {
                int row = idx >> 4, c = (idx & 15) * 8;
                int4 v = *reinterpret_cast<const int4*>(Wb + (size_t)(ch * 32 + row) * 128 + c);
                *reinterpret_cast<int4*>(&sW[row * 136 + c]) = v;
            }
        }
        __syncthreads();

#pragma unroll
        for (int kt = 0; kt < 2; kt++) {
            uint32_t aF[2][4], bF[4][4];
#pragma unroll
            for (int rt = 0; rt < 2; rt++) {
                uint32_t ad = smem_u32(&sA[(rw * 32 + rt * 16 + (lane & 15)) * 40 +
                                           kt * 16 + (lane >> 4) * 8]);
                ldsm_x4(aF[rt], ad);
            }
#pragma unroll
            for (int g = 0; g < 4; g++) {
                uint32_t ad = smem_u32(&sW[(kt * 16 + (lane & 15)) * 136 +
                                           cw * 64 + g * 16 + (lane >> 4) * 8]);
                ldsm_x4_t(bF[g], ad);
            }
#pragma unroll
            for (int rt = 0; rt < 2; rt++)
#pragma unroll
                for (int g = 0; g < 4; g++) {
                    mma16816(acc[rt][2 * g],     aF[rt], bF[g][0], bF[g][1]);
                    mma16816(acc[rt][2 * g + 1], aF[rt], bF[g][2], bF[g][3]);
                }
        }
        __syncthreads();
    }

    // epilogue
#pragma unroll
    for (int rt = 0; rt < 2; rt++) {
        int row0 = rw * 32 + rt * 16 + (lane >> 2);
#pragma unroll
        for (int g = 0; g < 8; g++) {
            int col = cw * 64 + g * 8 + (lane & 3) * 2;
#pragma unroll
            for (int h = 0; h < 2; h++) {
                int node = nbase + row0 + h * 8;
                if (node >= n) continue;
                float v0 = acc[rt][g][h * 2 + 0];
                float v1 = acc[rt][g][h * 2 + 1];
                if (L == 1) {
                    v0 = fmaxf(v0 + bias[col], 0.f);
                    v1 = fmaxf(v1 + bias[col + 1], 0.f);
                    __nv_bfloat16 h0, l0, h1, l1;
                    split_bf16(v0, h0, l0);
                    split_bf16(v1, h1, l1);
                    __nv_bfloat162 hp; hp.x = h0; hp.y = h1;
                    __nv_bfloat162 lp; lp.x = l0; lp.y = l1;
                    *reinterpret_cast<__nv_bfloat162*>(&g_A2[(size_t)node * 256 + col]) = hp;
                    *reinterpret_cast<__nv_bfloat162*>(&g_A2[(size_t)node * 256 + 128 + col]) = lp;
                } else {
                    if (col < 64) {
                        float2 p; p.x = v0; p.y = v1;
                        *reinterpret_cast<float2*>(&g_t2l[(size_t)node * 64 + col]) = p;
                    } else {
                        float2 p; p.x = v0 + bias[col - 64]; p.y = v1 + bias[col - 63];
                        *reinterpret_cast<float2*>(&g_t2r[(size_t)node * 64 + col - 64]) = p;
                    }
                }
            }
        }
    }
}

// ---------------- fused gather2 + softmax + Wg GEMM + out init -----------------
__global__ void __launch_bounds__(256)
sage2_post_kernel(const float* __restrict__ Wg, const float* __restrict__ bg,
                  float* __restrict__ out, int n) {
    __shared__ __align__(16) float sW[F2 * F2];
    __shared__ float sB[F2];
    __shared__ float sS[8][F2];
    int tid = threadIdx.x;
#pragma unroll
    for (int i = tid; i < F2 * F2 / 4; i += 256)
        reinterpret_cast<float4*>(sW)[i] = reinterpret_cast<const float4*>(Wg)[i];
    if (tid < F2) sB[tid] = bg[tid];
    __syncthreads();

    int warp = tid >> 5, lane = tid & 31;
    int node = blockIdx.x * 8 + warp;
    if (node >= n) return;

    int beg = g_rowptr[node], end = g_rowptr[node + 1];
    float2 acc = make_float2(0.f, 0.f);
    for (int chunk = beg; chunk < end; chunk += 32) {
        int myidx = (chunk + lane < end) ? g_csrc[chunk + lane] : 0;
        int m = min(32, end - chunk);
        int j = 0;
        for (; j + 4 <= m; j += 4) {
            int s0 = __shfl_sync(0xffffffffu, myidx, j);
            int s1 = __shfl_sync(0xffffffffu, myidx, j + 1);
            int s2 = __shfl_sync(0xffffffffu, myidx, j + 2);
            int s3 = __shfl_sync(0xffffffffu, myidx, j + 3);
            float2 v0 = *reinterpret_cast<const float2*>(g_t2l + (size_t)s0 * F2 + lane * 2);
            float2 v1 = *reinterpret_cast<const float2*>(g_t2l + (size_t)s1 * F2 + lane * 2);
            float2 v2 = *reinterpret_cast<const float2*>(g_t2l + (size_t)s2 * F2 + lane * 2);
            float2 v3 = *reinterpret_cast<const float2*>(g_t2l + (size_t)s3 * F2 + lane * 2);
            acc.x += v0.x + v1.x + v2.x + v3.x;
            acc.y += v0.y + v1.y + v2.y + v3.y;
        }
        for (; j < m; j++) {
            int s = __shfl_sync(0xffffffffu, myidx, j);
            float2 v = *reinterpret_cast<const float2*>(g_t2l + (size_t)s * F2 + lane * 2);
            acc.x += v.x; acc.y += v.y;
        }
    }
    int deg = end - beg;
    float r = 1.f / fmaxf((float)deg, 1.f);
    float2 tr = *reinterpret_cast<const float2*>(g_t2r + (size_t)node * F2 + lane * 2);
    float h0 = acc.x * r + tr.x;
    float h1 = acc.y * r + tr.y;

    float mx = fmaxf(h0, h1);
#pragma unroll
    for (int o = 16; o; o >>= 1) mx = fmaxf(mx, __shfl_xor_sync(0xffffffffu, mx, o));
    float e0 = __expf(h0 - mx), e1 = __expf(h1 - mx);
    float sm = e0 + e1;
#pragma unroll
    for (int o = 16; o; o >>= 1) sm += __shfl_xor_sync(0xffffffffu, sm, o);
    float inv = 1.f / sm;
    sS[warp][lane * 2]     = e0 * inv;
    sS[warp][lane * 2 + 1] = e1 * inv;
    __syncwarp();

    float a0 = 0.f, a1 = 0.f;
#pragma unroll
    for (int k = 0; k < F2; k++) {
        float s = sS[warp][k];
        a0 += s * sW[k * F2 + lane];
        a1 += s * sW[k * F2 + lane + 32];
    }
    float di = rsqrtf((float)deg + 1.0f);
    float y0 = a0 * di, y1 = a1 * di;
    g_y[(size_t)node * F2 + lane]      = y0;
    g_y[(size_t)node * F2 + lane + 32] = y1;
    if (lane == 0) g_dinv[node] = di;
    out[(size_t)node * F2 + lane]      = y0 * di + sB[lane];
    out[(size_t)node * F2 + lane + 32] = y1 * di + sB[lane + 32];
}

// ---------------- GCN gather ---------------------------------------------------
__global__ void __launch_bounds__(256)
gcn_gather_kernel(float* __restrict__ out, int n) {
    int w = (blockIdx.x * blockDim.x + threadIdx.x) >> 5;
    if (w >= n) return;
    int lane = threadIdx.x & 31;

    int beg = g_rowptr[w], end = g_rowptr[w + 1];
    float2 acc = make_float2(0.f, 0.f);
    for (int chunk = beg; chunk < end; chunk += 32) {
        int myidx = (chunk + lane < end) ? g_csrc[chunk + lane] : 0;
        int m = min(32, end - chunk);
        int j = 0;
        for (; j + 4 <= m; j += 4) {
            int s0 = __shfl_sync(0xffffffffu, myidx, j);
            int s1 = __shfl_sync(0xffffffffu, myidx, j + 1);
            int s2 = __shfl_sync(0xffffffffu, myidx, j + 2);
            int s3 = __shfl_sync(0xffffffffu, myidx, j + 3);
            float2 v0 = *reinterpret_cast<const float2*>(g_y + (size_t)s0 * F2 + lane * 2);
            float2 v1 = *reinterpret_cast<const float2*>(g_y + (size_t)s1 * F2 + lane * 2);
            float2 v2 = *reinterpret_cast<const float2*>(g_y + (size_t)s2 * F2 + lane * 2);
            float2 v3 = *reinterpret_cast<const float2*>(g_y + (size_t)s3 * F2 + lane * 2);
            acc.x += v0.x + v1.x + v2.x + v3.x;
            acc.y += v0.y + v1.y + v2.y + v3.y;
        }
        for (; j < m; j++) {
            int s = __shfl_sync(0xffffffffu, myidx, j);
            float2 v = *reinterpret_cast<const float2*>(g_y + (size_t)s * F2 + lane * 2);
            acc.x += v.x; acc.y += v.y;
        }
    }
    float di = g_dinv[w];
    float* o = out + (size_t)w * F2 + lane * 2;
    o[0] += di * acc.x;
    o[1] += di * acc.y;
}

// ---------------- launch -------------------------------------------------------
extern "C" void kernel_launch(void* const* d_in, const int* in_sizes, int n_in,
                              void* d_out, int out_size) {
    const float* x   = nullptr;
    const void*  idx = nullptr;
    const float *W1l = nullptr, *W1r = nullptr, *b1l = nullptr;
    const float *W2l = nullptr, *W2r = nullptr, *b2l = nullptr;
    const float *Wg  = nullptr, *bg  = nullptr;

    for (int i = 0; i < n_in; i++) {
        int sz = in_sizes[i];
        const void* p = d_in[i];
        switch (sz) {
            case 6400000: x = (const float*)p; break;
            case 1600000: idx = p; break;
            case 16384:  if (!W1l) W1l = (const float*)p; else W1r = (const float*)p; break;
            case 8192:   if (!W2l) W2l = (const float*)p; else W2r = (const float*)p; break;
            case 4096:   Wg = (const float*)p; break;
            case 128:    b1l = (const float*)p; break;
            case 64:     if (!b2l) b2l = (const float*)p; else bg = (const float*)p; break;
            default: break;
        }
    }

    float* out = (float*)d_out;
    const int n = 50000;
    const int E = 800000;

    int eb = (E + 255) / 256;
    int wb = (n * 32 + 255) / 256;
    int nb = (n + 255) / 256;
    int mb = (n + 127) / 128;     // 391 row-tiles for mma GEMMs

    // CSR build + conversions (independent prep)
    init_kernel<<<nb, 256>>>(n);
    probe_kernel<<<1, 32>>>(idx);
    convx_kernel<<<(n * 64 + 255) / 256, 256>>>(x, n);
    convw_kernel<<<(147456 + 255) / 256, 256>>>(W1l, W1r, W2l, W2r);
    decode_kernel<<<eb, 256>>>(idx, E);
    scanA_kernel<<<nb, 256>>>(n);
    scanB_kernel<<<1, 256>>>(nb);
    scanC_kernel<<<nb, 256>>>(n, E);
    fill_kernel<<<eb, 256>>>(E);

    // Layer 1: gather (writes agg hi/lo panels) + HMMA GEMM -> A2 panels
    gather1_kernel<<<wb, 256>>>(x, n);
    mma_gemm_kernel<24, 1><<<mb, 256>>>(b1l, n);

    // Layer 2: HMMA GEMM -> t2l | t2r, then fused gather+softmax+Wg
    mma_gemm_kernel<12, 2><<<mb, 256>>>(b2l, n);
    sage2_post_kernel<<<(n + 7) / 8, 256>>>(Wg, bg, out, n);

    // GCN neighbor term
    gcn_gather_kernel<<<wb, 256>>>(out, n);
}

// round 15
// speedup vs baseline: 1.5239x; 1.0102x over previous
#include <cuda_runtime.h>
#include <cuda_bf16.h>
#include <math.h>
#include <stdint.h>

// Problem constants
#define MAXN 50000
#define MAXE 800000
#define F1   128   // F_IN and H
#define F2   64    // C

// ---------------- scratch (__device__ globals; no allocs allowed) --------------
// A1 layout per node (512 bf16): [agg_hi(128) | agg_lo(128) | x_hi(128) | x_lo(128)]
// A2 layout per node (256 bf16): [h1_hi(128) | h1_lo(128)]
__device__ __align__(16) __nv_bfloat16 g_A1[(size_t)MAXN * 512];
__device__ __align__(16) __nv_bfloat16 g_A2[(size_t)MAXN * 256];
__device__ __align__(16) __nv_bfloat16 g_W1[768 * 128];  // blocked split W for layer1
__device__ __align__(16) __nv_bfloat16 g_W2[384 * 128];  // blocked split W for layer2
__device__ __align__(16) float g_t2l[(size_t)MAXN * F2];
__device__ __align__(16) float g_t2r[(size_t)MAXN * F2];
__device__ __align__(16) float g_y  [(size_t)MAXN * F2];
__device__ __align__(16) float g_dinv[MAXN];
__device__ __align__(16) int   g_csrc[MAXE];
__device__ __align__(16) int   g_cnt [MAXN];
__device__ __align__(16) int   g_rowptr[MAXN + 1];
__device__ __align__(16) int   g_cursor[MAXN];
#define NB_SCAN ((MAXN + 255) / 256)
__device__ __align__(16) int   g_bsum[NB_SCAN];
__device__ int g_isi64;

// ---------------- mma helpers ---------------------------------------------------
__device__ __forceinline__ uint32_t smem_u32(const void* p) {
    return (uint32_t)__cvta_generic_to_shared(p);
}
__device__ __forceinline__ void ldsm_x4(uint32_t* r, uint32_t a) {
    asm volatile("ldmatrix.sync.aligned.m8n8.x4.shared.b16 {%0,%1,%2,%3}, [%4];"
        : "=r"(r[0]), "=r"(r[1]), "=r"(r[2]), "=r"(r[3]) : "r"(a));
}
__device__ __forceinline__ void ldsm_x4_t(uint32_t* r, uint32_t a) {
    asm volatile("ldmatrix.sync.aligned.m8n8.x4.trans.shared.b16 {%0,%1,%2,%3}, [%4];"
        : "=r"(r[0]), "=r"(r[1]), "=r"(r[2]), "=r"(r[3]) : "r"(a));
}
__device__ __forceinline__ void mma16816(float* d, const uint32_t* a,
                                         uint32_t b0, uint32_t b1) {
    asm volatile("mma.sync.aligned.m16n8k16.row.col.f32.bf16.bf16.f32 "
        "{%0,%1,%2,%3}, {%4,%5,%6,%7}, {%8,%9}, {%0,%1,%2,%3};"
        : "+f"(d[0]), "+f"(d[1]), "+f"(d[2]), "+f"(d[3])
        : "r"(a[0]), "r"(a[1]), "r"(a[2]), "r"(a[3]), "r"(b0), "r"(b1));
}
__device__ __forceinline__ void split_bf16(float v, __nv_bfloat16& hi, __nv_bfloat16& lo) {
    hi = __float2bfloat16(v);
    lo = __float2bfloat16(v - __bfloat162float(hi));
}

// ---------------- fused prep: convx | convw | init | probe ---------------------
// blocks [0,12500): convx ; [12500,13076): convw ; [13076,13272): init cnt ;
// block 13272: probe idx dtype
__global__ void __launch_bounds__(256)
prep_kernel(const float* __restrict__ x,
            const float* __restrict__ W1l, const float* __restrict__ W1r,
            const float* __restrict__ W2l, const float* __restrict__ W2r,
            const void* __restrict__ idxv, int n) {
    int b = blockIdx.x;
    int tid = threadIdx.x;
    if (b < 12500) {
        int i = b * 256 + tid;
        if (i < n * 64) {
            int node = i >> 6;
            int c = (i & 63) * 2;
            float2 v = *reinterpret_cast<const float2*>(x + (size_t)node * F1 + c);
            __nv_bfloat16 h0, l0, h1, l1;
            split_bf16(v.x, h0, l0);
            split_bf16(v.y, h1, l1);
            __nv_bfloat162 hp; hp.x = h0; hp.y = h1;
            __nv_bfloat162 lp; lp.x = l0; lp.y = l1;
            *reinterpret_cast<__nv_bfloat162*>(&g_A1[(size_t)node * 512 + 256 + c]) = hp;
            *reinterpret_cast<__nv_bfloat162*>(&g_A1[(size_t)node * 512 + 384 + c]) = lp;
        }
    } else if (b < 13076) {
        int i = (b - 12500) * 256 + tid;     // 0..147455
        if (i < 98304) {
            int r = i >> 7, c = i & 127;
            int blk = r >> 7, rr = r & 127;
            float v = (blk < 3) ? W1l[rr * 128 + c] : W1r[rr * 128 + c];
            __nv_bfloat16 hi, lo;
            split_bf16(v, hi, lo);
            g_W1[i] = (blk == 2 || blk == 5) ? lo : hi;
        } else {
            int i2 = i - 98304;
            int r = i2 >> 7, c = i2 & 127;
            int blk = r >> 7, rr = r & 127;
            float v = (c < 64) ? W2l[rr * 64 + c] : W2r[rr * 64 + (c - 64)];
            __nv_bfloat16 hi, lo;
            split_bf16(v, hi, lo);
            g_W2[i2] = (blk == 2) ? lo : hi;
        }
    } else if (b < 13272) {
        int i = (b - 13076) * 256 + tid;
        if (i < n) g_cnt[i] = 0;
    } else {
        if (tid == 0) {
            const long long* p = (const long long*)idxv;
            int ok = 1;
            for (int i = 0; i < 64; i++) {
                long long v = p[i];
                if (v < 0 || v >= 2147483648LL) { ok = 0; break; }
            }
            g_isi64 = ok;
        }
    }
}

// ---------------- decode: degree count only ------------------------------------
__global__ void decode_kernel(const void* __restrict__ idxv, int E) {
    int e = blockIdx.x * blockDim.x + threadIdx.x;
    if (e >= E) return;
    int d = g_isi64 ? (int)((const long long*)idxv)[E + e]
                    : ((const int*)idxv)[E + e];
    atomicAdd(&g_cnt[d], 1);
}

// ---------------- scanA: per-block exclusive scan + block sums -----------------
__global__ void __launch_bounds__(256) scanA_kernel(int n) {
    __shared__ int wsum[8];
    int tid = threadIdx.x, lane = tid & 31, wid = tid >> 5;
    int i = blockIdx.x * 256 + tid;
    int v = (i < n) ? g_cnt[i] : 0;
    int x = v;
#pragma unroll
    for (int o = 1; o < 32; o <<= 1) {
        int t = __shfl_up_sync(0xffffffffu, x, o);
        if (lane >= o) x += t;
    }
    if (lane == 31) wsum[wid] = x;
    __syncthreads();
    if (wid == 0 && lane < 8) {
        int y = wsum[lane];
#pragma unroll
        for (int o = 1; o < 8; o <<= 1) {
            int t = __shfl_up_sync(0x000000ffu, y, o);
            if (lane >= o) y += t;
        }
        wsum[lane] = y;
    }
    __syncthreads();
    int excl = (wid ? wsum[wid - 1] : 0) + x - v;
    if (i < n) g_rowptr[i] = excl;
    if (tid == 0) g_bsum[blockIdx.x] = wsum[7];
}

// ---------------- scanC: inline carry reduction + offset add -------------------
__global__ void __launch_bounds__(256) scanC_kernel(int n, int E) {
    __shared__ int ssum[8];
    int tid = threadIdx.x, lane = tid & 31, wid = tid >> 5;
    int bid = blockIdx.x;
    int v = (tid < bid) ? g_bsum[tid] : 0;    // bid <= 195 < 256
#pragma unroll
    for (int o = 16; o; o >>= 1) v += __shfl_xor_sync(0xffffffffu, v, o);
    if (lane == 0) ssum[wid] = v;
    __syncthreads();
    int carry = ssum[0] + ssum[1] + ssum[2] + ssum[3] +
                ssum[4] + ssum[5] + ssum[6] + ssum[7];
    int i = bid * 256 + tid;
    if (i < n) {
        int val = g_rowptr[i] + carry;
        g_rowptr[i] = val;
        g_cursor[i] = val;
    }
    if (i == 0) g_rowptr[n] = E;
}

// ---------------- CSR fill (re-reads idx; it is L2-hot) ------------------------
__global__ void fill_kernel(const void* __restrict__ idxv, int E) {
    int e = blockIdx.x * blockDim.x + threadIdx.x;
    if (e >= E) return;
    int s, d;
    if (g_isi64) {
        const long long* p = (const long long*)idxv;
        s = (int)p[e];
        d = (int)p[E + e];
    } else {
        const int* p = (const int*)idxv;
        s = p[e];
        d = p[E + e];
    }
    int pos = atomicAdd(&g_cursor[d], 1);
    g_csrc[pos] = s;
}

// ---------------- SAGE1 gather -> mean -> bf16 split into A1 -------------------
__global__ void __launch_bounds__(256)
gather1_kernel(const float* __restrict__ feat, int n) {
    int w = (blockIdx.x * blockDim.x + threadIdx.x) >> 5;
    if (w >= n) return;
    int lane = threadIdx.x & 31;

    int beg = g_rowptr[w], end = g_rowptr[w + 1];
    float4 acc = make_float4(0.f, 0.f, 0.f, 0.f);
    for (int chunk = beg; chunk < end; chunk += 32) {
        int myidx = (chunk + lane < end) ? g_csrc[chunk + lane] : 0;
        int m = min(32, end - chunk);
        int j = 0;
        for (; j + 4 <= m; j += 4) {
            int s0 = __shfl_sync(0xffffffffu, myidx, j);
            int s1 = __shfl_sync(0xffffffffu, myidx, j + 1);
            int s2 = __shfl_sync(0xffffffffu, myidx, j + 2);
            int s3 = __shfl_sync(0xffffffffu, myidx, j + 3);
            float4 v0 = *reinterpret_cast<const float4*>(feat + (size_t)s0 * F1 + lane * 4);
            float4 v1 = *reinterpret_cast<const float4*>(feat + (size_t)s1 * F1 + lane * 4);
            float4 v2 = *reinterpret_cast<const float4*>(feat + (size_t)s2 * F1 + lane * 4);
            float4 v3 = *reinterpret_cast<const float4*>(feat + (size_t)s3 * F1 + lane * 4);
            acc.x += v0.x + v1.x + v2.x + v3.x;
            acc.y += v0.y + v1.y + v2.y + v3.y;
            acc.z += v0.z + v1.z + v2.z + v3.z;
            acc.w += v0.w + v1.w + v2.w + v3.w;
        }
        for (; j < m; j++) {
            int s = __shfl_sync(0xffffffffu, myidx, j);
            float4 v = *reinterpret_cast<const float4*>(feat + (size_t)s * F1 + lane * 4);
            acc.x += v.x; acc.y += v.y; acc.z += v.z; acc.w += v.w;
        }
    }
    float r = 1.f / fmaxf((float)(end - beg), 1.f);
    float v[4] = {acc.x * r, acc.y * r, acc.z * r, acc.w * r};
    __nv_bfloat16 h[4], l[4];
#pragma unroll
    for (int j = 0; j < 4; j++) split_bf16(v[j], h[j], l[j]);
    __nv_bfloat162 hp0; hp0.x = h[0]; hp0.y = h[1];
    __nv_bfloat162 hp1; hp1.x = h[2]; hp1.y = h[3];
    __nv_bfloat162 lp0; lp0.x = l[0]; lp0.y = l[1];
    __nv_bfloat162 lp1; lp1.x = l[2]; lp1.y = l[3];
    size_t base = (size_t)w * 512 + lane * 4;
    *reinterpret_cast<__nv_bfloat162*>(&g_A1[base])           = hp0;
    *reinterpret_cast<__nv_bfloat162*>(&g_A1[base + 2])       = hp1;
    *reinterpret_cast<__nv_bfloat162*>(&g_A1[base + 128])     = lp0;
    *reinterpret_cast<__nv_bfloat162*>(&g_A1[base + 130])     = lp1;
}

// ---------------- HMMA GEMM (operands selected device-side) --------------------
// L==1: C = relu(... + b1l) -> split into A2 panels
// L==2: C cols 0-63 -> t2l ; cols 64-127 -> t2r (+ b2l)
template <int KCHUNKS, int L>
__global__ void __launch_bounds__(256)
mma_gemm_kernel(const float* __restrict__ bias, int n) {
    const __nv_bfloat16* __restrict__ A  = (L == 1) ? g_A1 : g_A2;
    const __nv_bfloat16* __restrict__ Wb = (L == 1) ? g_W1 : g_W2;
    const int astride = (L == 1) ? 512 : 256;

    __shared__ __align__(16) __nv_bfloat16 sA[128 * 40];
    __shared__ __align__(16) __nv_bfloat16 sW[32 * 136];

    int tid = threadIdx.x;
    int wid = tid >> 5, lane = tid & 31;
    int rw = wid & 3;
    int cw = wid >> 2;
    int nbase = blockIdx.x * 128;

    float acc[2][8][4];
#pragma unroll
    for (int a = 0; a < 2; a++)
#pragma unroll
        for (int b = 0; b < 8; b++)
#pragma unroll
            for (int c = 0; c < 4; c++) acc[a][b][c] = 0.f;

    for (int ch = 0; ch < KCHUNKS; ch++) {
        int blk = ch >> 2;
        int aoff;
        if (L == 1) {
            const int lut[6] = {0, 128, 0, 256, 384, 256};
            aoff = lut[blk] + (ch & 3) * 32;
        } else {
            const int lut[3] = {0, 128, 0};
            aoff = lut[blk] + (ch & 3) * 32;
        }
        {
            int idx = tid;
#pragma unroll
            for (int it = 0; it < 2; it++, idx += 256) {
                int row = idx >> 2, q = (idx & 3) * 8;
                int node = nbase + row;
                int4 v = make_int4(0, 0, 0, 0);
                if (node < n)
                    v = *reinterpret_cast<const int4*>(A + (size_t)node * astride + aoff + q);
                *reinterpret_cast<int4*>(&sA[row * 40 + q]) = v;
            }
        }
        {
            int idx = tid;
#pragma unroll
            for (int it = 0; it < 2; it++, idx += 256) {
                int row = idx >> 4, c = (idx & 15) * 8;
                int4 v = *reinterpret_cast<const int4*>(Wb + (size_t)(ch * 32 + row) * 128 + c);
                *reinterpret_cast<int4*>(&sW[row * 136 + c]) = v;
            }
        }
        __syncthreads();

#pragma unroll
        for (int kt = 0; kt < 2; kt++) {
            uint32_t aF[2][4], bF[4][4];
#pragma unroll
            for (int rt = 0; rt < 2; rt++) {
                uint32_t ad = smem_u32(&sA[(rw * 32 + rt * 16 + (lane & 15)) * 40 +
                                           kt * 16 + (lane >> 4) * 8]);
                ldsm_x4(aF[rt], ad);
            }
#pragma unroll
            for (int g = 0; g < 4; g++) {
                uint32_t ad = smem_u32(&sW[(kt * 16 + (lane & 15)) * 136 +
                                           cw * 64 + g * 16 + (lane >> 4) * 8]);
                ldsm_x4_t(bF[g], ad);
            }
#pragma unroll
            for (int rt = 0; rt < 2; rt++)
#pragma unroll
                for (int g = 0; g < 4; g++) {
                    mma16816(acc[rt][2 * g],     aF[rt], bF[g][0], bF[g][1]);
                    mma16816(acc[rt][2 * g + 1], aF[rt], bF[g][2], bF[g][3]);
                }
        }
        __syncthreads();
    }

#pragma unroll
    for (int rt = 0; rt < 2; rt++) {
        int row0 = rw * 32 + rt * 16 + (lane >> 2);
#pragma unroll
        for (int g = 0; g < 8; g++) {
            int col = cw * 64 + g * 8 + (lane & 3) * 2;
#pragma unroll
            for (int h = 0; h < 2; h++) {
                int node = nbase + row0 + h * 8;
                if (node >= n) continue;
                float v0 = acc[rt][g][h * 2 + 0];
                float v1 = acc[rt][g][h * 2 + 1];
                if (L == 1) {
                    v0 = fmaxf(v0 + bias[col], 0.f);
                    v1 = fmaxf(v1 + bias[col + 1], 0.f);
                    __nv_bfloat16 h0, l0, h1, l1;
                    split_bf16(v0, h0, l0);
                    split_bf16(v1, h1, l1);
                    __nv_bfloat162 hp; hp.x = h0; hp.y = h1;
                    __nv_bfloat162 lp; lp.x = l0; lp.y = l1;
                    *reinterpret_cast<__nv_bfloat162*>(&g_A2[(size_t)node * 256 + col]) = hp;
                    *reinterpret_cast<__nv_bfloat162*>(&g_A2[(size_t)node * 256 + 128 + col]) = lp;
                } else {
                    if (col < 64) {
                        float2 p; p.x = v0; p.y = v1;
                        *reinterpret_cast<float2*>(&g_t2l[(size_t)node * 64 + col]) = p;
                    } else {
                        float2 p; p.x = v0 + bias[col - 64]; p.y = v1 + bias[col - 63];
                        *reinterpret_cast<float2*>(&g_t2r[(size_t)node * 64 + col - 64]) = p;
                    }
                }
            }
        }
    }
}

// ---------------- fused gather2 + softmax + Wg GEMM + out init -----------------
// 32 nodes per block (warp handles 4 serially) to amortize the 16KB sW load.
__global__ void __launch_bounds__(256)
sage2_post_kernel(const float* __restrict__ Wg, const float* __restrict__ bg,
                  float* __restrict__ out, int n) {
    __shared__ __align__(16) float sW[F2 * F2];
    __shared__ float sB[F2];
    __shared__ float sS[8][F2];
    int tid = threadIdx.x;
#pragma unroll
    for (int i = tid; i < F2 * F2 / 4; i += 256)
        reinterpret_cast<float4*>(sW)[i] = reinterpret_cast<const float4*>(Wg)[i];
    if (tid < F2) sB[tid] = bg[tid];
    __syncthreads();

    int warp = tid >> 5, lane = tid & 31;

#pragma unroll 1
    for (int it = 0; it < 4; it++) {
        int node = blockIdx.x * 32 + warp * 4 + it;
        if (node >= n) continue;

        int beg = g_rowptr[node], end = g_rowptr[node + 1];
        float2 acc = make_float2(0.f, 0.f);
        for (int chunk = beg; chunk < end; chunk += 32) {
            int myidx = (chunk + lane < end) ? g_csrc[chunk + lane] : 0;
            int m = min(32, end - chunk);
            int j = 0;
            for (; j + 8 <= m; j += 8) {
                float2 v[8];
#pragma unroll
                for (int q = 0; q < 8; q++) {
                    int s = __shfl_sync(0xffffffffu, myidx, j + q);
                    v[q] = *reinterpret_cast<const float2*>(g_t2l + (size_t)s * F2 + lane * 2);
                }
#pragma unroll
                for (int q = 0; q < 8; q++) { acc.x += v[q].x; acc.y += v[q].y; }
            }
            for (; j < m; j++) {
                int s = __shfl_sync(0xffffffffu, myidx, j);
                float2 v = *reinterpret_cast<const float2*>(g_t2l + (size_t)s * F2 + lane * 2);
                acc.x += v.x; acc.y += v.y;
            }
        }
        int deg = end - beg;
        float r = 1.f / fmaxf((float)deg, 1.f);
        float2 tr = *reinterpret_cast<const float2*>(g_t2r + (size_t)node * F2 + lane * 2);
        float h0 = acc.x * r + tr.x;
        float h1 = acc.y * r + tr.y;

        float mx = fmaxf(h0, h1);
#pragma unroll
        for (int o = 16; o; o >>= 1) mx = fmaxf(mx, __shfl_xor_sync(0xffffffffu, mx, o));
        float e0 = __expf(h0 - mx), e1 = __expf(h1 - mx);
        float sm = e0 + e1;
#pragma unroll
        for (int o = 16; o; o >>= 1) sm += __shfl_xor_sync(0xffffffffu, sm, o);
        float inv = 1.f / sm;
        sS[warp][lane * 2]     = e0 * inv;
        sS[warp][lane * 2 + 1] = e1 * inv;
        __syncwarp();

        float a0 = 0.f, a1 = 0.f;
#pragma unroll
        for (int k = 0; k < F2; k++) {
            float s = sS[warp][k];
            a0 += s * sW[k * F2 + lane];
            a1 += s * sW[k * F2 + lane + 32];
        }
        float di = rsqrtf((float)deg + 1.0f);
        float y0 = a0 * di, y1 = a1 * di;
        g_y[(size_t)node * F2 + lane]      = y0;
        g_y[(size_t)node * F2 + lane + 32] = y1;
        if (lane == 0) g_dinv[node] = di;
        out[(size_t)node * F2 + lane]      = y0 * di + sB[lane];
        out[(size_t)node * F2 + lane + 32] = y1 * di + sB[lane + 32];
        __syncwarp();
    }
}

// ---------------- GCN gather ---------------------------------------------------
__global__ void __launch_bounds__(256)
gcn_gather_kernel(float* __restrict__ out, int n) {
    int w = (blockIdx.x * blockDim.x + threadIdx.x) >> 5;
    if (w >= n) return;
    int lane = threadIdx.x & 31;

    int beg = g_rowptr[w], end = g_rowptr[w + 1];
    float2 acc = make_float2(0.f, 0.f);
    for (int chunk = beg; chunk < end; chunk += 32) {
        int myidx = (chunk + lane < end) ? g_csrc[chunk + lane] : 0;
        int m = min(32, end - chunk);
        int j = 0;
        for (; j + 8 <= m; j += 8) {
            float2 v[8];
#pragma unroll
            for (int q = 0; q < 8; q++) {
                int s = __shfl_sync(0xffffffffu, myidx, j + q);
                v[q] = *reinterpret_cast<const float2*>(g_y + (size_t)s * F2 + lane * 2);
            }
#pragma unroll
            for (int q = 0; q < 8; q++) { acc.x += v[q].x; acc.y += v[q].y; }
        }
        for (; j < m; j++) {
            int s = __shfl_sync(0xffffffffu, myidx, j);
            float2 v = *reinterpret_cast<const float2*>(g_y + (size_t)s * F2 + lane * 2);
            acc.x += v.x; acc.y += v.y;
        }
    }
    float di = g_dinv[w];
    float* o = out + (size_t)w * F2 + lane * 2;
    o[0] += di * acc.x;
    o[1] += di * acc.y;
}

// ---------------- launch -------------------------------------------------------
extern "C" void kernel_launch(void* const* d_in, const int* in_sizes, int n_in,
                              void* d_out, int out_size) {
    const float* x   = nullptr;
    const void*  idx = nullptr;
    const float *W1l = nullptr, *W1r = nullptr, *b1l = nullptr;
    const float *W2l = nullptr, *W2r = nullptr, *b2l = nullptr;
    const float *Wg  = nullptr, *bg  = nullptr;

    for (int i = 0; i < n_in; i++) {
        int sz = in_sizes[i];
        const void* p = d_in[i];
        switch (sz) {
            case 6400000: x = (const float*)p; break;
            case 1600000: idx = p; break;
            case 16384:  if (!W1l) W1l = (const float*)p; else W1r = (const float*)p; break;
            case 8192:   if (!W2l) W2l = (const float*)p; else W2r = (const float*)p; break;
            case 4096:   Wg = (const float*)p; break;
            case 128:    b1l = (const float*)p; break;
            case 64:     if (!b2l) b2l = (const float*)p; else bg = (const float*)p; break;
            default: break;
        }
    }

    float* out = (float*)d_out;
    const int n = 50000;
    const int E = 800000;

    int eb = (E + 255) / 256;
    int wb = (n * 32 + 255) / 256;
    int nb = (n + 255) / 256;     // 196
    int mb = (n + 127) / 128;     // 391

    // Fused prep (convx | convw | init | probe), then CSR chain
    prep_kernel<<<13273, 256>>>(x, W1l, W1r, W2l, W2r, idx, n);
    decode_kernel<<<eb, 256>>>(idx, E);
    scanA_kernel<<<nb, 256>>>(n);
    scanC_kernel<<<nb, 256>>>(n, E);
    fill_kernel<<<eb, 256>>>(idx, E);

    // Layer 1
    gather1_kernel<<<wb, 256>>>(x, n);
    mma_gemm_kernel<24, 1><<<mb, 256>>>(b1l, n);

    // Layer 2
    mma_gemm_kernel<12, 2><<<mb, 256>>>(b2l, n);
    sage2_post_kernel<<<(n + 31) / 32, 256>>>(Wg, bg, out, n);

    // GCN neighbor term
    gcn_gather_kernel<<<wb, 256>>>(out, n);
}